// round 2
// baseline (speedup 1.0000x reference)
#include <cuda_runtime.h>
#include <math.h>

#define DIM   384
#define HID   1536
#define BATCH 4
#define SEQ   2048
#define NTOK  (BATCH*SEQ)   /* 8192 tokens */
#define HEADS 6
#define DH    64

// ---------------- scratch (device globals; no allocation allowed) ----------
__device__ float g_ln  [NTOK * DIM];      //  12.6 MB (reused for ln1 & ln2)
__device__ float g_qkv [NTOK * 3 * DIM];  //  37.7 MB
__device__ float g_attn[NTOK * DIM];      //  12.6 MB
__device__ float g_x1  [NTOK * DIM];      //  12.6 MB
__device__ float g_h   [NTOK * HID];      //  50.3 MB

// ---------------- LayerNorm: one warp per 384-elem row ---------------------
__global__ __launch_bounds__(256) void ln_kernel(
    const float* __restrict__ x, const float* __restrict__ g,
    const float* __restrict__ b, float* __restrict__ out)
{
    int warp = (blockIdx.x * blockDim.x + threadIdx.x) >> 5;
    int lane = threadIdx.x & 31;
    if (warp >= NTOK) return;
    const float* xr = x + (size_t)warp * DIM;

    float v[12];
    float s = 0.f;
#pragma unroll
    for (int i = 0; i < 12; i++) { v[i] = xr[lane + i * 32]; s += v[i]; }
#pragma unroll
    for (int o = 16; o > 0; o >>= 1) s += __shfl_xor_sync(0xffffffffu, s, o);
    float mu = s * (1.0f / DIM);
    float vs = 0.f;
#pragma unroll
    for (int i = 0; i < 12; i++) { float d = v[i] - mu; vs += d * d; }
#pragma unroll
    for (int o = 16; o > 0; o >>= 1) vs += __shfl_xor_sync(0xffffffffu, vs, o);
    float rstd = rsqrtf(vs * (1.0f / DIM) + 1e-6f);

    float* orow = out + (size_t)warp * DIM;
#pragma unroll
    for (int i = 0; i < 12; i++) {
        int c = lane + i * 32;
        orow[c] = (v[i] - mu) * rstd * g[c] + b[c];
    }
}

// ---------------- SGEMM 128x128x16, 8x8 micro-tile, fused epilogue ---------
// EPI: 0 = bias only, 1 = bias + exact GELU, 2 = bias + residual add
template <int EPI>
__global__ __launch_bounds__(256) void gemm_kernel(
    const float* __restrict__ A, const float* __restrict__ W,
    const float* __restrict__ bias, const float* __restrict__ res,
    float* __restrict__ C, int M, int K, int N)
{
    __shared__ float As[16][132];
    __shared__ float Ws[16][132];

    const int bm = blockIdx.y * 128;
    const int bn = blockIdx.x * 128;
    const int tid = threadIdx.x;
    const int tx = tid & 15, ty = tid >> 4;

    float acc[8][8];
#pragma unroll
    for (int i = 0; i < 8; i++)
#pragma unroll
        for (int j = 0; j < 8; j++) acc[i][j] = 0.f;

    const int ar = tid >> 2;          // A row within tile (and +64)
    const int ak = (tid & 3) << 2;    // A k-quad
    const int wk = tid >> 5;          // W k row (and +8)
    const int wn = (tid & 31) << 2;   // W n-quad

    for (int k0 = 0; k0 < K; k0 += 16) {
        float4 a0 = *(const float4*)&A[(size_t)(bm + ar)      * K + k0 + ak];
        float4 a1 = *(const float4*)&A[(size_t)(bm + ar + 64) * K + k0 + ak];
        float4 w0 = *(const float4*)&W[(size_t)(k0 + wk)     * N + bn + wn];
        float4 w1 = *(const float4*)&W[(size_t)(k0 + wk + 8) * N + bn + wn];

        As[ak + 0][ar] = a0.x; As[ak + 1][ar] = a0.y;
        As[ak + 2][ar] = a0.z; As[ak + 3][ar] = a0.w;
        As[ak + 0][ar + 64] = a1.x; As[ak + 1][ar + 64] = a1.y;
        As[ak + 2][ar + 64] = a1.z; As[ak + 3][ar + 64] = a1.w;
        *(float4*)&Ws[wk][wn]     = w0;
        *(float4*)&Ws[wk + 8][wn] = w1;
        __syncthreads();

#pragma unroll
        for (int kk = 0; kk < 16; kk++) {
            float4 alo = *(const float4*)&As[kk][ty * 4];
            float4 ahi = *(const float4*)&As[kk][64 + ty * 4];
            float4 blo = *(const float4*)&Ws[kk][tx * 4];
            float4 bhi = *(const float4*)&Ws[kk][64 + tx * 4];
            float a[8] = {alo.x, alo.y, alo.z, alo.w, ahi.x, ahi.y, ahi.z, ahi.w};
            float b[8] = {blo.x, blo.y, blo.z, blo.w, bhi.x, bhi.y, bhi.z, bhi.w};
#pragma unroll
            for (int i = 0; i < 8; i++)
#pragma unroll
                for (int j = 0; j < 8; j++)
                    acc[i][j] = fmaf(a[i], b[j], acc[i][j]);
        }
        __syncthreads();
    }

#pragma unroll
    for (int i = 0; i < 8; i++) {
        int row = bm + ((i < 4) ? (ty * 4 + i) : (64 + ty * 4 + i - 4));
#pragma unroll
        for (int jh = 0; jh < 2; jh++) {
            int col0 = bn + ((jh == 0) ? (tx * 4) : (64 + tx * 4));
            float4 v;
            float* vp = &v.x;
#pragma unroll
            for (int j = 0; j < 4; j++) {
                float t = acc[i][jh * 4 + j] + bias[col0 + j];
                if (EPI == 1)
                    t = 0.5f * t * (1.0f + erff(t * 0.70710678118654752f));
                vp[j] = t;
            }
            if (EPI == 2) {
                float4 r4 = *(const float4*)&res[(size_t)row * N + col0];
                v.x += r4.x; v.y += r4.y; v.z += r4.z; v.w += r4.w;
            }
            *(float4*)&C[(size_t)row * N + col0] = v;
        }
    }
}

// ---------------- Fused flash attention ------------------------------------
// grid: (SEQ/64, BATCH*HEADS), 256 threads. 64 q-rows/block, 32-key tiles.
__global__ __launch_bounds__(256) void attn_kernel(
    const float* __restrict__ qkv, float* __restrict__ out)
{
    __shared__ float Qs[64][68];
    __shared__ float Ks[32][68];
    __shared__ float Vs[32][68];
    __shared__ float Ps[64][36];

    const int bh = blockIdx.y;
    const int b = bh / HEADS, h = bh % HEADS;
    const int q0 = blockIdx.x * 64;
    const int tid = threadIdx.x;
    const int tx = tid & 15, ty = tid >> 4;
    const size_t rstride = 3 * DIM;                       // 1152
    const size_t base = (size_t)b * SEQ * rstride + h * DH;

    // Q tile: 64 rows x 64 d = 1024 float4 quads, 4 per thread
#pragma unroll
    for (int t = 0; t < 4; t++) {
        int q = tid + t * 256;
        int r = q >> 4, dq = (q & 15) * 4;
        float4 v = *(const float4*)&qkv[base + (size_t)(q0 + r) * rstride + dq];
        *(float4*)&Qs[r][dq] = v;
    }

    float m[4], l[4], acc_o[4][4];
#pragma unroll
    for (int i = 0; i < 4; i++) {
        m[i] = -1e30f; l[i] = 0.f;
#pragma unroll
        for (int j = 0; j < 4; j++) acc_o[i][j] = 0.f;
    }

    for (int kt = 0; kt < SEQ; kt += 32) {
        // K/V tiles: 32 x 64 each = 512 quads -> 2 per thread each
#pragma unroll
        for (int t = 0; t < 2; t++) {
            int q = tid + t * 256;
            int r = q >> 4, dq = (q & 15) * 4;
            float4 kv = *(const float4*)&qkv[base + DIM     + (size_t)(kt + r) * rstride + dq];
            float4 vv = *(const float4*)&qkv[base + 2 * DIM + (size_t)(kt + r) * rstride + dq];
            *(float4*)&Ks[r][dq] = kv;
            *(float4*)&Vs[r][dq] = vv;
        }
        __syncthreads();   // covers Q tile too on first iteration

        // S = Q @ K^T (64x32 tile; thread owns 4 rows x 2 keys)
        float s[4][2];
#pragma unroll
        for (int i = 0; i < 4; i++) { s[i][0] = 0.f; s[i][1] = 0.f; }
#pragma unroll
        for (int d0 = 0; d0 < DH; d0 += 4) {
            float4 a[4], bb[2];
#pragma unroll
            for (int i = 0; i < 4; i++) a[i]  = *(const float4*)&Qs[4 * ty + i][d0];
#pragma unroll
            for (int j = 0; j < 2; j++) bb[j] = *(const float4*)&Ks[2 * tx + j][d0];
#pragma unroll
            for (int i = 0; i < 4; i++)
#pragma unroll
                for (int j = 0; j < 2; j++) {
                    s[i][j] = fmaf(a[i].x, bb[j].x, s[i][j]);
                    s[i][j] = fmaf(a[i].y, bb[j].y, s[i][j]);
                    s[i][j] = fmaf(a[i].z, bb[j].z, s[i][j]);
                    s[i][j] = fmaf(a[i].w, bb[j].w, s[i][j]);
                }
        }

        // online softmax (reduce across the 16 tx lanes; xor<16 stays in-half)
        const float scale = 0.125f;   // 64^-0.5
#pragma unroll
        for (int i = 0; i < 4; i++) {
            s[i][0] *= scale; s[i][1] *= scale;
            float mx = fmaxf(s[i][0], s[i][1]);
#pragma unroll
            for (int o = 8; o > 0; o >>= 1)
                mx = fmaxf(mx, __shfl_xor_sync(0xffffffffu, mx, o));
            float mn = fmaxf(m[i], mx);
            float alpha = __expf(m[i] - mn);
            float p0 = __expf(s[i][0] - mn);
            float p1 = __expf(s[i][1] - mn);
            float ls = p0 + p1;
#pragma unroll
            for (int o = 8; o > 0; o >>= 1)
                ls += __shfl_xor_sync(0xffffffffu, ls, o);
            l[i] = l[i] * alpha + ls;
            m[i] = mn;
            Ps[4 * ty + i][2 * tx + 0] = p0;
            Ps[4 * ty + i][2 * tx + 1] = p1;
#pragma unroll
            for (int j = 0; j < 4; j++) acc_o[i][j] *= alpha;
        }
        __syncthreads();

        // O += P @ V (thread owns 4 rows x 4 d-cols at tx*4)
#pragma unroll
        for (int jq = 0; jq < 8; jq++) {
            float ar[4][4];
#pragma unroll
            for (int i = 0; i < 4; i++) {
                float4 a4 = *(const float4*)&Ps[4 * ty + i][jq * 4];
                ar[i][0] = a4.x; ar[i][1] = a4.y; ar[i][2] = a4.z; ar[i][3] = a4.w;
            }
#pragma unroll
            for (int u = 0; u < 4; u++) {
                float4 bv = *(const float4*)&Vs[jq * 4 + u][tx * 4];
#pragma unroll
                for (int i = 0; i < 4; i++) {
                    acc_o[i][0] = fmaf(ar[i][u], bv.x, acc_o[i][0]);
                    acc_o[i][1] = fmaf(ar[i][u], bv.y, acc_o[i][1]);
                    acc_o[i][2] = fmaf(ar[i][u], bv.z, acc_o[i][2]);
                    acc_o[i][3] = fmaf(ar[i][u], bv.w, acc_o[i][3]);
                }
            }
        }
        __syncthreads();
    }

    // normalize + write [B,N,C] with C = h*64 + d
#pragma unroll
    for (int i = 0; i < 4; i++) {
        int r = q0 + 4 * ty + i;
        float inv = 1.0f / l[i];
        float4 v = make_float4(acc_o[i][0] * inv, acc_o[i][1] * inv,
                               acc_o[i][2] * inv, acc_o[i][3] * inv);
        *(float4*)&out[((size_t)(b * SEQ + r)) * DIM + h * DH + tx * 4] = v;
    }
}

// ---------------- launch ----------------------------------------------------
extern "C" void kernel_launch(void* const* d_in, const int* in_sizes, int n_in,
                              void* d_out, int out_size)
{
    const float* x      = (const float*)d_in[0];
    const float* w_qkv  = (const float*)d_in[1];
    const float* b_qkv  = (const float*)d_in[2];
    const float* w_proj = (const float*)d_in[3];
    const float* b_proj = (const float*)d_in[4];
    const float* w_fc1  = (const float*)d_in[5];
    const float* b_fc1  = (const float*)d_in[6];
    const float* w_fc2  = (const float*)d_in[7];
    const float* b_fc2  = (const float*)d_in[8];
    const float* g1     = (const float*)d_in[9];
    const float* beta1  = (const float*)d_in[10];
    const float* g2     = (const float*)d_in[11];
    const float* beta2  = (const float*)d_in[12];
    float* out = (float*)d_out;

    float *p_ln, *p_qkv, *p_attn, *p_x1, *p_h;
    cudaGetSymbolAddress((void**)&p_ln,   g_ln);
    cudaGetSymbolAddress((void**)&p_qkv,  g_qkv);
    cudaGetSymbolAddress((void**)&p_attn, g_attn);
    cudaGetSymbolAddress((void**)&p_x1,   g_x1);
    cudaGetSymbolAddress((void**)&p_h,    g_h);

    // 1) LN1
    ln_kernel<<<NTOK / 8, 256>>>(x, g1, beta1, p_ln);
    // 2) QKV GEMM: [8192,384] @ [384,1152] + bias
    gemm_kernel<0><<<dim3(3 * DIM / 128, NTOK / 128), 256>>>(
        p_ln, w_qkv, b_qkv, nullptr, p_qkv, NTOK, DIM, 3 * DIM);
    // 3) fused flash attention
    attn_kernel<<<dim3(SEQ / 64, BATCH * HEADS), 256>>>(p_qkv, p_attn);
    // 4) proj GEMM + bias + residual(x)
    gemm_kernel<2><<<dim3(DIM / 128, NTOK / 128), 256>>>(
        p_attn, w_proj, b_proj, x, p_x1, NTOK, DIM, DIM);
    // 5) LN2
    ln_kernel<<<NTOK / 8, 256>>>(p_x1, g2, beta2, p_ln);
    // 6) FC1 GEMM + bias + exact GELU
    gemm_kernel<1><<<dim3(HID / 128, NTOK / 128), 256>>>(
        p_ln, w_fc1, b_fc1, nullptr, p_h, NTOK, DIM, HID);
    // 7) FC2 GEMM + bias + residual(x1) -> d_out
    gemm_kernel<2><<<dim3(DIM / 128, NTOK / 128), 256>>>(
        p_h, w_fc2, b_fc2, p_x1, out, NTOK, HID, DIM);
}

// round 3
// speedup vs baseline: 1.3051x; 1.3051x over previous
#include <cuda_runtime.h>
#include <math.h>
#include <stdint.h>

#define DIM   384
#define HID   1536
#define BATCH 4
#define SEQ   2048
#define NTOK  (BATCH*SEQ)   /* 8192 tokens */
#define HEADS 6
#define DH    64

// ---------------- scratch (device globals; no allocation allowed) ----------
__device__ float g_ln  [NTOK * DIM];
__device__ float g_qkv [NTOK * 3 * DIM];
__device__ float g_attn[NTOK * DIM];
__device__ float g_x1  [NTOK * DIM];
__device__ float g_h   [NTOK * HID];

// ---------------- helpers ---------------------------------------------------
__device__ __forceinline__ float f2tf32(float x) {
    uint32_t u;
    asm("cvt.rna.tf32.f32 %0, %1;" : "=r"(u) : "f"(x));
    return __uint_as_float(u);
}

__device__ __forceinline__ void mma_tf32(float c[4], const uint32_t a[4], const uint32_t b[2]) {
    asm volatile(
        "mma.sync.aligned.m16n8k8.row.col.f32.tf32.tf32.f32 "
        "{%0,%1,%2,%3}, {%4,%5,%6,%7}, {%8,%9}, {%0,%1,%2,%3};"
        : "+f"(c[0]), "+f"(c[1]), "+f"(c[2]), "+f"(c[3])
        : "r"(a[0]), "r"(a[1]), "r"(a[2]), "r"(a[3]), "r"(b[0]), "r"(b[1]));
}

// ---------------- LayerNorm: one warp per 384-elem row ---------------------
__global__ __launch_bounds__(256) void ln_kernel(
    const float* __restrict__ x, const float* __restrict__ g,
    const float* __restrict__ b, float* __restrict__ out)
{
    int warp = (blockIdx.x * blockDim.x + threadIdx.x) >> 5;
    int lane = threadIdx.x & 31;
    if (warp >= NTOK) return;
    const float* xr = x + (size_t)warp * DIM;

    float v[12];
    float s = 0.f;
#pragma unroll
    for (int i = 0; i < 12; i++) { v[i] = xr[lane + i * 32]; s += v[i]; }
#pragma unroll
    for (int o = 16; o > 0; o >>= 1) s += __shfl_xor_sync(0xffffffffu, s, o);
    float mu = s * (1.0f / DIM);
    float vs = 0.f;
#pragma unroll
    for (int i = 0; i < 12; i++) { float d = v[i] - mu; vs += d * d; }
#pragma unroll
    for (int o = 16; o > 0; o >>= 1) vs += __shfl_xor_sync(0xffffffffu, vs, o);
    float rstd = rsqrtf(vs * (1.0f / DIM) + 1e-6f);

    float* orow = out + (size_t)warp * DIM;
#pragma unroll
    for (int i = 0; i < 12; i++) {
        int c = lane + i * 32;
        orow[c] = (v[i] - mu) * rstd * g[c] + b[c];
    }
}

// ---------------- tf32 tensor-core GEMM ------------------------------------
// 128x128 block tile, 256 threads = 8 warps (2 warp-rows x 4 warp-cols),
// each warp 64x32 via m16n8k8 tf32 mma (4 m-frags x 4 n-frags).
// EPI: 0 = bias only, 1 = bias + exact GELU, 2 = bias + residual add
template <int EPI>
__global__ __launch_bounds__(256, 2) void gemm_tc(
    const float* __restrict__ A, const float* __restrict__ W,
    const float* __restrict__ bias, const float* __restrict__ res,
    float* __restrict__ C, int M, int K, int N)
{
    __shared__ float As[128][36];   // [m][k], k-block = 32, pad->conflict-free frags
    __shared__ float Bs[32][136];   // [k][n], pad 136 -> conflict-free frags

    const int tid  = threadIdx.x;
    const int lane = tid & 31;
    const int wid  = tid >> 5;
    const int wm   = wid >> 2;      // 0..1
    const int wn   = wid & 3;       // 0..3
    const int bm   = blockIdx.y * 128;
    const int bn   = blockIdx.x * 128;

    float acc[4][4][4];
#pragma unroll
    for (int mf = 0; mf < 4; mf++)
#pragma unroll
        for (int nf = 0; nf < 4; nf++)
#pragma unroll
            for (int i = 0; i < 4; i++) acc[mf][nf][i] = 0.f;

    // A fill: thread t covers row (mi*32 + t/8), k-quad (t%8)*4
    const int a_kq = (tid & 7) << 2;
    const int a_mr = tid >> 3;           // 0..31
    // B fill: thread t covers k row (t/32 + 8*i), n-quad (t%32)*4
    const int b_k  = tid >> 5;           // 0..7
    const int b_n  = (lane) << 2;

    const int fr = lane >> 2;            // frag row 0..7
    const int fc = lane & 3;             // frag col 0..3

    for (int k0 = 0; k0 < K; k0 += 32) {
#pragma unroll
        for (int mi = 0; mi < 4; mi++) {
            int m = mi * 32 + a_mr;
            float4 a4 = *(const float4*)&A[(size_t)(bm + m) * K + k0 + a_kq];
            a4.x = f2tf32(a4.x); a4.y = f2tf32(a4.y);
            a4.z = f2tf32(a4.z); a4.w = f2tf32(a4.w);
            *(float4*)&As[m][a_kq] = a4;
        }
#pragma unroll
        for (int ki = 0; ki < 4; ki++) {
            int kk = b_k + ki * 8;
            float4 b4 = *(const float4*)&W[(size_t)(k0 + kk) * N + bn + b_n];
            b4.x = f2tf32(b4.x); b4.y = f2tf32(b4.y);
            b4.z = f2tf32(b4.z); b4.w = f2tf32(b4.w);
            *(float4*)&Bs[kk][b_n] = b4;
        }
        __syncthreads();

#pragma unroll
        for (int ks = 0; ks < 4; ks++) {
            const int kb = ks * 8;
            uint32_t afr[4][4], bfr[4][2];
#pragma unroll
            for (int mf = 0; mf < 4; mf++) {
                int r = wm * 64 + mf * 16 + fr;
                int c = kb + fc;
                afr[mf][0] = __float_as_uint(As[r][c]);
                afr[mf][1] = __float_as_uint(As[r + 8][c]);
                afr[mf][2] = __float_as_uint(As[r][c + 4]);
                afr[mf][3] = __float_as_uint(As[r + 8][c + 4]);
            }
#pragma unroll
            for (int nf = 0; nf < 4; nf++) {
                int kk = kb + fc;
                int n = wn * 32 + nf * 8 + fr;
                bfr[nf][0] = __float_as_uint(Bs[kk][n]);
                bfr[nf][1] = __float_as_uint(Bs[kk + 4][n]);
            }
#pragma unroll
            for (int mf = 0; mf < 4; mf++)
#pragma unroll
                for (int nf = 0; nf < 4; nf++)
                    mma_tf32(acc[mf][nf], afr[mf], bfr[nf]);
        }
        __syncthreads();
    }

    // epilogue: c0,c1 at (row, col..col+1); c2,c3 at (row+8, col..col+1)
#pragma unroll
    for (int mf = 0; mf < 4; mf++) {
#pragma unroll
        for (int half = 0; half < 2; half++) {
            int row = bm + wm * 64 + mf * 16 + fr + half * 8;
#pragma unroll
            for (int nf = 0; nf < 4; nf++) {
                int col = bn + wn * 32 + nf * 8 + 2 * fc;
                float v0 = acc[mf][nf][half * 2 + 0] + bias[col];
                float v1 = acc[mf][nf][half * 2 + 1] + bias[col + 1];
                if (EPI == 1) {
                    v0 = 0.5f * v0 * (1.0f + erff(v0 * 0.70710678118654752f));
                    v1 = 0.5f * v1 * (1.0f + erff(v1 * 0.70710678118654752f));
                }
                if (EPI == 2) {
                    float2 r2 = *(const float2*)&res[(size_t)row * N + col];
                    v0 += r2.x; v1 += r2.y;
                }
                float2 o; o.x = v0; o.y = v1;
                *(float2*)&C[(size_t)row * N + col] = o;
            }
        }
    }
}

// ---------------- Fused flash attention (unchanged FFMA; next-round target)
__global__ __launch_bounds__(256) void attn_kernel(
    const float* __restrict__ qkv, float* __restrict__ out)
{
    __shared__ float Qs[64][68];
    __shared__ float Ks[32][68];
    __shared__ float Vs[32][68];
    __shared__ float Ps[64][36];

    const int bh = blockIdx.y;
    const int b = bh / HEADS, h = bh % HEADS;
    const int q0 = blockIdx.x * 64;
    const int tid = threadIdx.x;
    const int tx = tid & 15, ty = tid >> 4;
    const size_t rstride = 3 * DIM;
    const size_t base = (size_t)b * SEQ * rstride + h * DH;

#pragma unroll
    for (int t = 0; t < 4; t++) {
        int q = tid + t * 256;
        int r = q >> 4, dq = (q & 15) * 4;
        float4 v = *(const float4*)&qkv[base + (size_t)(q0 + r) * rstride + dq];
        *(float4*)&Qs[r][dq] = v;
    }

    float m[4], l[4], acc_o[4][4];
#pragma unroll
    for (int i = 0; i < 4; i++) {
        m[i] = -1e30f; l[i] = 0.f;
#pragma unroll
        for (int j = 0; j < 4; j++) acc_o[i][j] = 0.f;
    }

    for (int kt = 0; kt < SEQ; kt += 32) {
#pragma unroll
        for (int t = 0; t < 2; t++) {
            int q = tid + t * 256;
            int r = q >> 4, dq = (q & 15) * 4;
            float4 kv = *(const float4*)&qkv[base + DIM     + (size_t)(kt + r) * rstride + dq];
            float4 vv = *(const float4*)&qkv[base + 2 * DIM + (size_t)(kt + r) * rstride + dq];
            *(float4*)&Ks[r][dq] = kv;
            *(float4*)&Vs[r][dq] = vv;
        }
        __syncthreads();

        float s[4][2];
#pragma unroll
        for (int i = 0; i < 4; i++) { s[i][0] = 0.f; s[i][1] = 0.f; }
#pragma unroll
        for (int d0 = 0; d0 < DH; d0 += 4) {
            float4 a[4], bb[2];
#pragma unroll
            for (int i = 0; i < 4; i++) a[i]  = *(const float4*)&Qs[4 * ty + i][d0];
#pragma unroll
            for (int j = 0; j < 2; j++) bb[j] = *(const float4*)&Ks[2 * tx + j][d0];
#pragma unroll
            for (int i = 0; i < 4; i++)
#pragma unroll
                for (int j = 0; j < 2; j++) {
                    s[i][j] = fmaf(a[i].x, bb[j].x, s[i][j]);
                    s[i][j] = fmaf(a[i].y, bb[j].y, s[i][j]);
                    s[i][j] = fmaf(a[i].z, bb[j].z, s[i][j]);
                    s[i][j] = fmaf(a[i].w, bb[j].w, s[i][j]);
                }
        }

        const float scale = 0.125f;
#pragma unroll
        for (int i = 0; i < 4; i++) {
            s[i][0] *= scale; s[i][1] *= scale;
            float mx = fmaxf(s[i][0], s[i][1]);
#pragma unroll
            for (int o = 8; o > 0; o >>= 1)
                mx = fmaxf(mx, __shfl_xor_sync(0xffffffffu, mx, o));
            float mn = fmaxf(m[i], mx);
            float alpha = __expf(m[i] - mn);
            float p0 = __expf(s[i][0] - mn);
            float p1 = __expf(s[i][1] - mn);
            float ls = p0 + p1;
#pragma unroll
            for (int o = 8; o > 0; o >>= 1)
                ls += __shfl_xor_sync(0xffffffffu, ls, o);
            l[i] = l[i] * alpha + ls;
            m[i] = mn;
            Ps[4 * ty + i][2 * tx + 0] = p0;
            Ps[4 * ty + i][2 * tx + 1] = p1;
#pragma unroll
            for (int j = 0; j < 4; j++) acc_o[i][j] *= alpha;
        }
        __syncthreads();

#pragma unroll
        for (int jq = 0; jq < 8; jq++) {
            float ar[4][4];
#pragma unroll
            for (int i = 0; i < 4; i++) {
                float4 a4 = *(const float4*)&Ps[4 * ty + i][jq * 4];
                ar[i][0] = a4.x; ar[i][1] = a4.y; ar[i][2] = a4.z; ar[i][3] = a4.w;
            }
#pragma unroll
            for (int u = 0; u < 4; u++) {
                float4 bv = *(const float4*)&Vs[jq * 4 + u][tx * 4];
#pragma unroll
                for (int i = 0; i < 4; i++) {
                    acc_o[i][0] = fmaf(ar[i][u], bv.x, acc_o[i][0]);
                    acc_o[i][1] = fmaf(ar[i][u], bv.y, acc_o[i][1]);
                    acc_o[i][2] = fmaf(ar[i][u], bv.z, acc_o[i][2]);
                    acc_o[i][3] = fmaf(ar[i][u], bv.w, acc_o[i][3]);
                }
            }
        }
        __syncthreads();
    }

#pragma unroll
    for (int i = 0; i < 4; i++) {
        int r = q0 + 4 * ty + i;
        float inv = 1.0f / l[i];
        float4 v = make_float4(acc_o[i][0] * inv, acc_o[i][1] * inv,
                               acc_o[i][2] * inv, acc_o[i][3] * inv);
        *(float4*)&out[((size_t)(b * SEQ + r)) * DIM + h * DH + tx * 4] = v;
    }
}

// ---------------- launch ----------------------------------------------------
extern "C" void kernel_launch(void* const* d_in, const int* in_sizes, int n_in,
                              void* d_out, int out_size)
{
    const float* x      = (const float*)d_in[0];
    const float* w_qkv  = (const float*)d_in[1];
    const float* b_qkv  = (const float*)d_in[2];
    const float* w_proj = (const float*)d_in[3];
    const float* b_proj = (const float*)d_in[4];
    const float* w_fc1  = (const float*)d_in[5];
    const float* b_fc1  = (const float*)d_in[6];
    const float* w_fc2  = (const float*)d_in[7];
    const float* b_fc2  = (const float*)d_in[8];
    const float* g1     = (const float*)d_in[9];
    const float* beta1  = (const float*)d_in[10];
    const float* g2     = (const float*)d_in[11];
    const float* beta2  = (const float*)d_in[12];
    float* out = (float*)d_out;

    float *p_ln, *p_qkv, *p_attn, *p_x1, *p_h;
    cudaGetSymbolAddress((void**)&p_ln,   g_ln);
    cudaGetSymbolAddress((void**)&p_qkv,  g_qkv);
    cudaGetSymbolAddress((void**)&p_attn, g_attn);
    cudaGetSymbolAddress((void**)&p_x1,   g_x1);
    cudaGetSymbolAddress((void**)&p_h,    g_h);

    // 1) LN1
    ln_kernel<<<NTOK / 8, 256>>>(x, g1, beta1, p_ln);
    // 2) QKV GEMM: [8192,384] @ [384,1152] + bias
    gemm_tc<0><<<dim3(3 * DIM / 128, NTOK / 128), 256>>>(
        p_ln, w_qkv, b_qkv, nullptr, p_qkv, NTOK, DIM, 3 * DIM);
    // 3) fused flash attention
    attn_kernel<<<dim3(SEQ / 64, BATCH * HEADS), 256>>>(p_qkv, p_attn);
    // 4) proj GEMM + bias + residual(x)
    gemm_tc<2><<<dim3(DIM / 128, NTOK / 128), 256>>>(
        p_attn, w_proj, b_proj, x, p_x1, NTOK, DIM, DIM);
    // 5) LN2
    ln_kernel<<<NTOK / 8, 256>>>(p_x1, g2, beta2, p_ln);
    // 6) FC1 GEMM + bias + exact GELU
    gemm_tc<1><<<dim3(HID / 128, NTOK / 128), 256>>>(
        p_ln, w_fc1, b_fc1, nullptr, p_h, NTOK, DIM, HID);
    // 7) FC2 GEMM + bias + residual(x1) -> d_out
    gemm_tc<2><<<dim3(DIM / 128, NTOK / 128), 256>>>(
        p_h, w_fc2, b_fc2, p_x1, out, NTOK, HID, DIM);
}

// round 5
// speedup vs baseline: 2.9931x; 2.2935x over previous
#include <cuda_runtime.h>
#include <math.h>
#include <stdint.h>

#define DIM   384
#define HID   1536
#define BATCH 4
#define SEQ   2048
#define NTOK  (BATCH*SEQ)   /* 8192 tokens */
#define HEADS 6
#define DH    64

// ---------------- scratch (device globals; no allocation allowed) ----------
__device__ float g_ln  [NTOK * DIM];
__device__ float g_qkv [NTOK * 3 * DIM];
__device__ float g_attn[NTOK * DIM];
__device__ float g_x1  [NTOK * DIM];
__device__ float g_h   [NTOK * HID];

// ---------------- helpers ---------------------------------------------------
__device__ __forceinline__ float f2tf32(float x) {
    uint32_t u;
    asm("cvt.rna.tf32.f32 %0, %1;" : "=r"(u) : "f"(x));
    return __uint_as_float(u);
}

__device__ __forceinline__ void mma_tf32(float c[4], const uint32_t a[4], const uint32_t b[2]) {
    asm volatile(
        "mma.sync.aligned.m16n8k8.row.col.f32.tf32.tf32.f32 "
        "{%0,%1,%2,%3}, {%4,%5,%6,%7}, {%8,%9}, {%0,%1,%2,%3};"
        : "+f"(c[0]), "+f"(c[1]), "+f"(c[2]), "+f"(c[3])
        : "r"(a[0]), "r"(a[1]), "r"(a[2]), "r"(a[3]), "r"(b[0]), "r"(b[1]));
}

// ---------------- LayerNorm: one warp per 384-elem row ---------------------
__global__ __launch_bounds__(256) void ln_kernel(
    const float* __restrict__ x, const float* __restrict__ g,
    const float* __restrict__ b, float* __restrict__ out)
{
    int warp = (blockIdx.x * blockDim.x + threadIdx.x) >> 5;
    int lane = threadIdx.x & 31;
    if (warp >= NTOK) return;
    const float* xr = x + (size_t)warp * DIM;

    float v[12];
    float s = 0.f;
#pragma unroll
    for (int i = 0; i < 12; i++) { v[i] = xr[lane + i * 32]; s += v[i]; }
#pragma unroll
    for (int o = 16; o > 0; o >>= 1) s += __shfl_xor_sync(0xffffffffu, s, o);
    float mu = s * (1.0f / DIM);
    float vs = 0.f;
#pragma unroll
    for (int i = 0; i < 12; i++) { float d = v[i] - mu; vs += d * d; }
#pragma unroll
    for (int o = 16; o > 0; o >>= 1) vs += __shfl_xor_sync(0xffffffffu, vs, o);
    float rstd = rsqrtf(vs * (1.0f / DIM) + 1e-6f);

    float* orow = out + (size_t)warp * DIM;
#pragma unroll
    for (int i = 0; i < 12; i++) {
        int c = lane + i * 32;
        orow[c] = (v[i] - mu) * rstd * g[c] + b[c];
    }
}

// ---------------- tf32 tensor-core GEMM ------------------------------------
template <int EPI>
__global__ __launch_bounds__(256, 2) void gemm_tc(
    const float* __restrict__ A, const float* __restrict__ W,
    const float* __restrict__ bias, const float* __restrict__ res,
    float* __restrict__ C, int M, int K, int N)
{
    __shared__ float As[128][36];
    __shared__ float Bs[32][136];

    const int tid  = threadIdx.x;
    const int lane = tid & 31;
    const int wid  = tid >> 5;
    const int wm   = wid >> 2;
    const int wn   = wid & 3;
    const int bm   = blockIdx.y * 128;
    const int bn   = blockIdx.x * 128;

    float acc[4][4][4];
#pragma unroll
    for (int mf = 0; mf < 4; mf++)
#pragma unroll
        for (int nf = 0; nf < 4; nf++)
#pragma unroll
            for (int i = 0; i < 4; i++) acc[mf][nf][i] = 0.f;

    const int a_kq = (tid & 7) << 2;
    const int a_mr = tid >> 3;
    const int b_k  = tid >> 5;
    const int b_n  = lane << 2;

    const int fr = lane >> 2;
    const int fc = lane & 3;

    for (int k0 = 0; k0 < K; k0 += 32) {
#pragma unroll
        for (int mi = 0; mi < 4; mi++) {
            int m = mi * 32 + a_mr;
            float4 a4 = *(const float4*)&A[(size_t)(bm + m) * K + k0 + a_kq];
            a4.x = f2tf32(a4.x); a4.y = f2tf32(a4.y);
            a4.z = f2tf32(a4.z); a4.w = f2tf32(a4.w);
            *(float4*)&As[m][a_kq] = a4;
        }
#pragma unroll
        for (int ki = 0; ki < 4; ki++) {
            int kk = b_k + ki * 8;
            float4 b4 = *(const float4*)&W[(size_t)(k0 + kk) * N + bn + b_n];
            b4.x = f2tf32(b4.x); b4.y = f2tf32(b4.y);
            b4.z = f2tf32(b4.z); b4.w = f2tf32(b4.w);
            *(float4*)&Bs[kk][b_n] = b4;
        }
        __syncthreads();

#pragma unroll
        for (int ks = 0; ks < 4; ks++) {
            const int kb = ks * 8;
            uint32_t afr[4][4], bfr[4][2];
#pragma unroll
            for (int mf = 0; mf < 4; mf++) {
                int r = wm * 64 + mf * 16 + fr;
                int c = kb + fc;
                afr[mf][0] = __float_as_uint(As[r][c]);
                afr[mf][1] = __float_as_uint(As[r + 8][c]);
                afr[mf][2] = __float_as_uint(As[r][c + 4]);
                afr[mf][3] = __float_as_uint(As[r + 8][c + 4]);
            }
#pragma unroll
            for (int nf = 0; nf < 4; nf++) {
                int kk = kb + fc;
                int n = wn * 32 + nf * 8 + fr;
                bfr[nf][0] = __float_as_uint(Bs[kk][n]);
                bfr[nf][1] = __float_as_uint(Bs[kk + 4][n]);
            }
#pragma unroll
            for (int mf = 0; mf < 4; mf++)
#pragma unroll
                for (int nf = 0; nf < 4; nf++)
                    mma_tf32(acc[mf][nf], afr[mf], bfr[nf]);
        }
        __syncthreads();
    }

#pragma unroll
    for (int mf = 0; mf < 4; mf++) {
#pragma unroll
        for (int half = 0; half < 2; half++) {
            int row = bm + wm * 64 + mf * 16 + fr + half * 8;
#pragma unroll
            for (int nf = 0; nf < 4; nf++) {
                int col = bn + wn * 32 + nf * 8 + 2 * fc;
                float v0 = acc[mf][nf][half * 2 + 0] + bias[col];
                float v1 = acc[mf][nf][half * 2 + 1] + bias[col + 1];
                if (EPI == 1) {
                    v0 = 0.5f * v0 * (1.0f + erff(v0 * 0.70710678118654752f));
                    v1 = 0.5f * v1 * (1.0f + erff(v1 * 0.70710678118654752f));
                }
                if (EPI == 2) {
                    float2 r2 = *(const float2*)&res[(size_t)row * N + col];
                    v0 += r2.x; v1 += r2.y;
                }
                float2 o; o.x = v0; o.y = v1;
                *(float2*)&C[(size_t)row * N + col] = o;
            }
        }
    }
}

// ---------------- tf32 tensor-core flash attention --------------------------
// grid (SEQ/64, BATCH*HEADS), 128 threads = 4 warps; warp w owns q-rows
// [16w, 16w+16). Key tiles of 32. All matmul via m16n8k8 tf32 mma.
__global__ __launch_bounds__(128) void attn_tc(
    const float* __restrict__ qkv, float* __restrict__ out)
{
    __shared__ float Qs[64][68];   // stride 68 % 32 = 4 -> row-frag reads conflict-free
    __shared__ float Ks[32][68];
    __shared__ float Vs[32][72];   // stride 72 % 32 = 8 -> fc-row B-frag reads conflict-free
    __shared__ float Ps[64][36];   // stride 36 % 32 = 4 -> A-frag reads conflict-free

    const int bh = blockIdx.y;
    const int b = bh / HEADS, h = bh % HEADS;
    const int q0 = blockIdx.x * 64;
    const int tid = threadIdx.x;
    const int lane = tid & 31;
    const int wid = tid >> 5;
    const int fr = lane >> 2, fc = lane & 3;
    const int r0 = wid * 16 + fr;           // this thread's first q-row in tile
    const size_t rstride = 3 * DIM;
    const size_t base = (size_t)b * SEQ * rstride + h * DH;

    // load Q (64x64), fold in softmax scale 0.125, convert tf32
#pragma unroll
    for (int t = 0; t < 8; t++) {
        int q = tid + t * 128;
        int r = q >> 4, dq = (q & 15) * 4;
        float4 v = *(const float4*)&qkv[base + (size_t)(q0 + r) * rstride + dq];
        v.x = f2tf32(v.x * 0.125f); v.y = f2tf32(v.y * 0.125f);
        v.z = f2tf32(v.z * 0.125f); v.w = f2tf32(v.w * 0.125f);
        *(float4*)&Qs[r][dq] = v;
    }

    float m0 = -1e30f, m1 = -1e30f, l0 = 0.f, l1 = 0.f;
    float acc_o[8][4];
#pragma unroll
    for (int nf = 0; nf < 8; nf++)
#pragma unroll
        for (int i = 0; i < 4; i++) acc_o[nf][i] = 0.f;

    for (int kt = 0; kt < SEQ; kt += 32) {
        // K,V tiles 32x64 each: 512 quads -> 4 per thread each
#pragma unroll
        for (int t = 0; t < 4; t++) {
            int q = tid + t * 128;
            int r = q >> 4, dq = (q & 15) * 4;
            float4 kv = *(const float4*)&qkv[base + DIM     + (size_t)(kt + r) * rstride + dq];
            float4 vv = *(const float4*)&qkv[base + 2 * DIM + (size_t)(kt + r) * rstride + dq];
            kv.x = f2tf32(kv.x); kv.y = f2tf32(kv.y);
            kv.z = f2tf32(kv.z); kv.w = f2tf32(kv.w);
            vv.x = f2tf32(vv.x); vv.y = f2tf32(vv.y);
            vv.z = f2tf32(vv.z); vv.w = f2tf32(vv.w);
            *(float4*)&Ks[r][dq] = kv;
            *(float4*)&Vs[r][dq] = vv;
        }
        __syncthreads();

        // S = Q @ K^T : 16 rows x 32 keys per warp (4 n-frags)
        float s[4][4];
#pragma unroll
        for (int nf = 0; nf < 4; nf++)
#pragma unroll
            for (int i = 0; i < 4; i++) s[nf][i] = 0.f;
#pragma unroll
        for (int ks = 0; ks < 8; ks++) {
            const int kb = ks * 8;
            uint32_t a[4];
            a[0] = __float_as_uint(Qs[r0][kb + fc]);
            a[1] = __float_as_uint(Qs[r0 + 8][kb + fc]);
            a[2] = __float_as_uint(Qs[r0][kb + fc + 4]);
            a[3] = __float_as_uint(Qs[r0 + 8][kb + fc + 4]);
#pragma unroll
            for (int nf = 0; nf < 4; nf++) {
                uint32_t bb[2];
                bb[0] = __float_as_uint(Ks[nf * 8 + fr][kb + fc]);
                bb[1] = __float_as_uint(Ks[nf * 8 + fr][kb + fc + 4]);
                mma_tf32(s[nf], a, bb);
            }
        }

        // online softmax on C-fragments (row stats: lanes sharing fr -> xor 1,2)
        float mx0 = -1e30f, mx1 = -1e30f;
#pragma unroll
        for (int nf = 0; nf < 4; nf++) {
            mx0 = fmaxf(mx0, fmaxf(s[nf][0], s[nf][1]));
            mx1 = fmaxf(mx1, fmaxf(s[nf][2], s[nf][3]));
        }
        mx0 = fmaxf(mx0, __shfl_xor_sync(0xffffffffu, mx0, 1));
        mx0 = fmaxf(mx0, __shfl_xor_sync(0xffffffffu, mx0, 2));
        mx1 = fmaxf(mx1, __shfl_xor_sync(0xffffffffu, mx1, 1));
        mx1 = fmaxf(mx1, __shfl_xor_sync(0xffffffffu, mx1, 2));
        float mn0 = fmaxf(m0, mx0), mn1 = fmaxf(m1, mx1);
        float al0 = __expf(m0 - mn0), al1 = __expf(m1 - mn1);
        float sum0 = 0.f, sum1 = 0.f;
#pragma unroll
        for (int nf = 0; nf < 4; nf++) {
            s[nf][0] = __expf(s[nf][0] - mn0);
            s[nf][1] = __expf(s[nf][1] - mn0);
            s[nf][2] = __expf(s[nf][2] - mn1);
            s[nf][3] = __expf(s[nf][3] - mn1);
            sum0 += s[nf][0] + s[nf][1];
            sum1 += s[nf][2] + s[nf][3];
        }
        sum0 += __shfl_xor_sync(0xffffffffu, sum0, 1);
        sum0 += __shfl_xor_sync(0xffffffffu, sum0, 2);
        sum1 += __shfl_xor_sync(0xffffffffu, sum1, 1);
        sum1 += __shfl_xor_sync(0xffffffffu, sum1, 2);
        l0 = l0 * al0 + sum0; l1 = l1 * al1 + sum1;
        m0 = mn0; m1 = mn1;
#pragma unroll
        for (int nf = 0; nf < 8; nf++) {
            acc_o[nf][0] *= al0; acc_o[nf][1] *= al0;
            acc_o[nf][2] *= al1; acc_o[nf][3] *= al1;
        }

        // stage P (C-layout -> A-layout) through warp-private smem rows
#pragma unroll
        for (int nf = 0; nf < 4; nf++) {
            float2 p01; p01.x = s[nf][0]; p01.y = s[nf][1];
            float2 p23; p23.x = s[nf][2]; p23.y = s[nf][3];
            *(float2*)&Ps[r0][nf * 8 + 2 * fc]     = p01;
            *(float2*)&Ps[r0 + 8][nf * 8 + 2 * fc] = p23;
        }
        __syncwarp();

        // O += P @ V : k = 32 keys (4 k-steps), n = 64 d (8 n-frags)
#pragma unroll
        for (int ks = 0; ks < 4; ks++) {
            const int kb = ks * 8;
            uint32_t a[4];
            a[0] = __float_as_uint(Ps[r0][kb + fc]);
            a[1] = __float_as_uint(Ps[r0 + 8][kb + fc]);
            a[2] = __float_as_uint(Ps[r0][kb + fc + 4]);
            a[3] = __float_as_uint(Ps[r0 + 8][kb + fc + 4]);
#pragma unroll
            for (int nf = 0; nf < 8; nf++) {
                uint32_t bb[2];
                bb[0] = __float_as_uint(Vs[kb + fc][nf * 8 + fr]);
                bb[1] = __float_as_uint(Vs[kb + fc + 4][nf * 8 + fr]);
                mma_tf32(acc_o[nf], a, bb);
            }
        }
        __syncthreads();
    }

    // normalize + write [B,N,C], C-col = h*64 + nf*8 + 2fc
    float inv0 = 1.0f / l0, inv1 = 1.0f / l1;
    const size_t obase = (size_t)(b * SEQ) * DIM + h * DH;
#pragma unroll
    for (int nf = 0; nf < 8; nf++) {
        int col = nf * 8 + 2 * fc;
        float2 o0; o0.x = acc_o[nf][0] * inv0; o0.y = acc_o[nf][1] * inv0;
        float2 o1; o1.x = acc_o[nf][2] * inv1; o1.y = acc_o[nf][3] * inv1;
        *(float2*)&out[obase + (size_t)(q0 + r0) * DIM + col]     = o0;
        *(float2*)&out[obase + (size_t)(q0 + r0 + 8) * DIM + col] = o1;
    }
}

// ---------------- launch ----------------------------------------------------
extern "C" void kernel_launch(void* const* d_in, const int* in_sizes, int n_in,
                              void* d_out, int out_size)
{
    const float* x      = (const float*)d_in[0];
    const float* w_qkv  = (const float*)d_in[1];
    const float* b_qkv  = (const float*)d_in[2];
    const float* w_proj = (const float*)d_in[3];
    const float* b_proj = (const float*)d_in[4];
    const float* w_fc1  = (const float*)d_in[5];
    const float* b_fc1  = (const float*)d_in[6];
    const float* w_fc2  = (const float*)d_in[7];
    const float* b_fc2  = (const float*)d_in[8];
    const float* g1     = (const float*)d_in[9];
    const float* beta1  = (const float*)d_in[10];
    const float* g2     = (const float*)d_in[11];
    const float* beta2  = (const float*)d_in[12];
    float* out = (float*)d_out;

    float *p_ln, *p_qkv, *p_attn, *p_x1, *p_h;
    cudaGetSymbolAddress((void**)&p_ln,   g_ln);
    cudaGetSymbolAddress((void**)&p_qkv,  g_qkv);
    cudaGetSymbolAddress((void**)&p_attn, g_attn);
    cudaGetSymbolAddress((void**)&p_x1,   g_x1);
    cudaGetSymbolAddress((void**)&p_h,    g_h);

    // 1) LN1
    ln_kernel<<<NTOK / 8, 256>>>(x, g1, beta1, p_ln);
    // 2) QKV GEMM: [8192,384] @ [384,1152] + bias
    gemm_tc<0><<<dim3(3 * DIM / 128, NTOK / 128), 256>>>(
        p_ln, w_qkv, b_qkv, nullptr, p_qkv, NTOK, DIM, 3 * DIM);
    // 3) tf32 tensor-core flash attention
    attn_tc<<<dim3(SEQ / 64, BATCH * HEADS), 128>>>(p_qkv, p_attn);
    // 4) proj GEMM + bias + residual(x)
    gemm_tc<2><<<dim3(DIM / 128, NTOK / 128), 256>>>(
        p_attn, w_proj, b_proj, x, p_x1, NTOK, DIM, DIM);
    // 5) LN2
    ln_kernel<<<NTOK / 8, 256>>>(p_x1, g2, beta2, p_ln);
    // 6) FC1 GEMM + bias + exact GELU
    gemm_tc<1><<<dim3(HID / 128, NTOK / 128), 256>>>(
        p_ln, w_fc1, b_fc1, nullptr, p_h, NTOK, DIM, HID);
    // 7) FC2 GEMM + bias + residual(x1) -> d_out
    gemm_tc<2><<<dim3(DIM / 128, NTOK / 128), 256>>>(
        p_h, w_fc2, b_fc2, p_x1, out, NTOK, HID, DIM);
}

// round 6
// speedup vs baseline: 3.2816x; 1.0964x over previous
#include <cuda_runtime.h>
#include <math.h>
#include <stdint.h>

#define DIM   384
#define HID   1536
#define BATCH 4
#define SEQ   2048
#define NTOK  (BATCH*SEQ)   /* 8192 tokens */
#define HEADS 6
#define DH    64

// ---------------- scratch (device globals; no allocation allowed) ----------
__device__ float g_ln  [NTOK * DIM];
__device__ float g_qkv [NTOK * 3 * DIM];
__device__ float g_attn[NTOK * DIM];
__device__ float g_x1  [NTOK * DIM];
__device__ float g_h   [NTOK * HID];

// ---------------- helpers ---------------------------------------------------
__device__ __forceinline__ void mma_tf32(float c[4], const uint32_t a[4], const uint32_t b[2]) {
    asm volatile(
        "mma.sync.aligned.m16n8k8.row.col.f32.tf32.tf32.f32 "
        "{%0,%1,%2,%3}, {%4,%5,%6,%7}, {%8,%9}, {%0,%1,%2,%3};"
        : "+f"(c[0]), "+f"(c[1]), "+f"(c[2]), "+f"(c[3])
        : "r"(a[0]), "r"(a[1]), "r"(a[2]), "r"(a[3]), "r"(b[0]), "r"(b[1]));
}

__device__ __forceinline__ uint32_t cvta_s(const void* p) {
    return (uint32_t)__cvta_generic_to_shared(p);
}
__device__ __forceinline__ void cpa16(uint32_t dst, const void* src) {
    asm volatile("cp.async.cg.shared.global [%0], [%1], 16;" :: "r"(dst), "l"(src));
}

// ---------------- LayerNorm: one warp per 384-elem row ---------------------
__global__ __launch_bounds__(256) void ln_kernel(
    const float* __restrict__ x, const float* __restrict__ g,
    const float* __restrict__ b, float* __restrict__ out)
{
    int warp = (blockIdx.x * blockDim.x + threadIdx.x) >> 5;
    int lane = threadIdx.x & 31;
    if (warp >= NTOK) return;
    const float* xr = x + (size_t)warp * DIM;

    float v[12];
    float s = 0.f;
#pragma unroll
    for (int i = 0; i < 12; i++) { v[i] = xr[lane + i * 32]; s += v[i]; }
#pragma unroll
    for (int o = 16; o > 0; o >>= 1) s += __shfl_xor_sync(0xffffffffu, s, o);
    float mu = s * (1.0f / DIM);
    float vs = 0.f;
#pragma unroll
    for (int i = 0; i < 12; i++) { float d = v[i] - mu; vs += d * d; }
#pragma unroll
    for (int o = 16; o > 0; o >>= 1) vs += __shfl_xor_sync(0xffffffffu, vs, o);
    float rstd = rsqrtf(vs * (1.0f / DIM) + 1e-6f);

    float* orow = out + (size_t)warp * DIM;
#pragma unroll
    for (int i = 0; i < 12; i++) {
        int c = lane + i * 32;
        orow[c] = (v[i] - mu) * rstd * g[c] + b[c];
    }
}

// ---------------- tf32 tensor-core GEMM, cp.async double-buffered ----------
// dyn smem: As[2][128][36] + Bs[2][32][136]  = 71680 bytes
#define AS(buf,m,k)  smem[(buf)*(128*36) + (m)*36 + (k)]
#define BS(buf,kk,n) smem[2*128*36 + (buf)*(32*136) + (kk)*136 + (n)]
#define GEMM_SMEM ((2*128*36 + 2*32*136) * 4)

template <int EPI>
__global__ __launch_bounds__(256, 2) void gemm_tc(
    const float* __restrict__ A, const float* __restrict__ W,
    const float* __restrict__ bias, const float* __restrict__ res,
    float* __restrict__ C, int M, int K, int N)
{
    extern __shared__ float smem[];

    const int tid  = threadIdx.x;
    const int lane = tid & 31;
    const int wid  = tid >> 5;
    const int wm   = wid >> 2;
    const int wn   = wid & 3;
    const int bm   = blockIdx.y * 128;
    const int bn   = blockIdx.x * 128;

    const int a_kq = (tid & 7) << 2;
    const int a_mr = tid >> 3;
    const int b_k  = tid >> 5;
    const int b_n  = lane << 2;
    const int fr   = lane >> 2;
    const int fc   = lane & 3;

    float acc[4][4][4];
#pragma unroll
    for (int mf = 0; mf < 4; mf++)
#pragma unroll
        for (int nf = 0; nf < 4; nf++)
#pragma unroll
            for (int i = 0; i < 4; i++) acc[mf][nf][i] = 0.f;

    const int NK = K >> 5;

    // prologue: stage 0
    {
#pragma unroll
        for (int mi = 0; mi < 4; mi++) {
            int m = mi * 32 + a_mr;
            cpa16(cvta_s(&AS(0, m, a_kq)), &A[(size_t)(bm + m) * K + a_kq]);
        }
#pragma unroll
        for (int ki = 0; ki < 4; ki++) {
            int kk = b_k + ki * 8;
            cpa16(cvta_s(&BS(0, kk, b_n)), &W[(size_t)kk * N + bn + b_n]);
        }
        asm volatile("cp.async.commit_group;");
    }

    for (int kb = 0; kb < NK; kb++) {
        const int buf = kb & 1;
        if (kb + 1 < NK) {
            const int k0 = (kb + 1) << 5;
            const int nb = buf ^ 1;
#pragma unroll
            for (int mi = 0; mi < 4; mi++) {
                int m = mi * 32 + a_mr;
                cpa16(cvta_s(&AS(nb, m, a_kq)), &A[(size_t)(bm + m) * K + k0 + a_kq]);
            }
#pragma unroll
            for (int ki = 0; ki < 4; ki++) {
                int kk = b_k + ki * 8;
                cpa16(cvta_s(&BS(nb, kk, b_n)), &W[(size_t)(k0 + kk) * N + bn + b_n]);
            }
            asm volatile("cp.async.commit_group;");
            asm volatile("cp.async.wait_group 1;");
        } else {
            asm volatile("cp.async.wait_group 0;");
        }
        __syncthreads();

#pragma unroll
        for (int ks = 0; ks < 4; ks++) {
            const int kb8 = ks * 8;
            uint32_t afr[4][4], bfr[4][2];
#pragma unroll
            for (int mf = 0; mf < 4; mf++) {
                int r = wm * 64 + mf * 16 + fr;
                int c = kb8 + fc;
                afr[mf][0] = __float_as_uint(AS(buf, r, c));
                afr[mf][1] = __float_as_uint(AS(buf, r + 8, c));
                afr[mf][2] = __float_as_uint(AS(buf, r, c + 4));
                afr[mf][3] = __float_as_uint(AS(buf, r + 8, c + 4));
            }
#pragma unroll
            for (int nf = 0; nf < 4; nf++) {
                int kk = kb8 + fc;
                int n = wn * 32 + nf * 8 + fr;
                bfr[nf][0] = __float_as_uint(BS(buf, kk, n));
                bfr[nf][1] = __float_as_uint(BS(buf, kk + 4, n));
            }
#pragma unroll
            for (int mf = 0; mf < 4; mf++)
#pragma unroll
                for (int nf = 0; nf < 4; nf++)
                    mma_tf32(acc[mf][nf], afr[mf], bfr[nf]);
        }
        __syncthreads();
    }

#pragma unroll
    for (int mf = 0; mf < 4; mf++) {
#pragma unroll
        for (int half = 0; half < 2; half++) {
            int row = bm + wm * 64 + mf * 16 + fr + half * 8;
#pragma unroll
            for (int nf = 0; nf < 4; nf++) {
                int col = bn + wn * 32 + nf * 8 + 2 * fc;
                float v0 = acc[mf][nf][half * 2 + 0] + bias[col];
                float v1 = acc[mf][nf][half * 2 + 1] + bias[col + 1];
                if (EPI == 1) {
                    v0 = 0.5f * v0 * (1.0f + erff(v0 * 0.70710678118654752f));
                    v1 = 0.5f * v1 * (1.0f + erff(v1 * 0.70710678118654752f));
                }
                if (EPI == 2) {
                    float2 r2 = *(const float2*)&res[(size_t)row * N + col];
                    v0 += r2.x; v1 += r2.y;
                }
                float2 o; o.x = v0; o.y = v1;
                *(float2*)&C[(size_t)row * N + col] = o;
            }
        }
    }
}

// ---------------- tf32 tensor-core flash attention --------------------------
__global__ __launch_bounds__(128) void attn_tc(
    const float* __restrict__ qkv, float* __restrict__ out)
{
    __shared__ float Qs[64][68];
    __shared__ float Ks[32][68];
    __shared__ float Vs[32][72];
    __shared__ float Ps[64][36];

    const int bh = blockIdx.y;
    const int b = bh / HEADS, h = bh % HEADS;
    const int q0 = blockIdx.x * 64;
    const int tid = threadIdx.x;
    const int lane = tid & 31;
    const int wid = tid >> 5;
    const int fr = lane >> 2, fc = lane & 3;
    const int r0 = wid * 16 + fr;
    const size_t rstride = 3 * DIM;
    const size_t base = (size_t)b * SEQ * rstride + h * DH;

    // load Q (64x64), fold in softmax scale 0.125 (HW truncates to tf32)
#pragma unroll
    for (int t = 0; t < 8; t++) {
        int q = tid + t * 128;
        int r = q >> 4, dq = (q & 15) * 4;
        float4 v = *(const float4*)&qkv[base + (size_t)(q0 + r) * rstride + dq];
        v.x *= 0.125f; v.y *= 0.125f; v.z *= 0.125f; v.w *= 0.125f;
        *(float4*)&Qs[r][dq] = v;
    }

    float m0 = -1e30f, m1 = -1e30f, l0 = 0.f, l1 = 0.f;
    float acc_o[8][4];
#pragma unroll
    for (int nf = 0; nf < 8; nf++)
#pragma unroll
        for (int i = 0; i < 4; i++) acc_o[nf][i] = 0.f;

    for (int kt = 0; kt < SEQ; kt += 32) {
#pragma unroll
        for (int t = 0; t < 4; t++) {
            int q = tid + t * 128;
            int r = q >> 4, dq = (q & 15) * 4;
            float4 kv = *(const float4*)&qkv[base + DIM     + (size_t)(kt + r) * rstride + dq];
            float4 vv = *(const float4*)&qkv[base + 2 * DIM + (size_t)(kt + r) * rstride + dq];
            *(float4*)&Ks[r][dq] = kv;
            *(float4*)&Vs[r][dq] = vv;
        }
        __syncthreads();

        float s[4][4];
#pragma unroll
        for (int nf = 0; nf < 4; nf++)
#pragma unroll
            for (int i = 0; i < 4; i++) s[nf][i] = 0.f;
#pragma unroll
        for (int ks = 0; ks < 8; ks++) {
            const int kb = ks * 8;
            uint32_t a[4];
            a[0] = __float_as_uint(Qs[r0][kb + fc]);
            a[1] = __float_as_uint(Qs[r0 + 8][kb + fc]);
            a[2] = __float_as_uint(Qs[r0][kb + fc + 4]);
            a[3] = __float_as_uint(Qs[r0 + 8][kb + fc + 4]);
#pragma unroll
            for (int nf = 0; nf < 4; nf++) {
                uint32_t bb[2];
                bb[0] = __float_as_uint(Ks[nf * 8 + fr][kb + fc]);
                bb[1] = __float_as_uint(Ks[nf * 8 + fr][kb + fc + 4]);
                mma_tf32(s[nf], a, bb);
            }
        }

        float mx0 = -1e30f, mx1 = -1e30f;
#pragma unroll
        for (int nf = 0; nf < 4; nf++) {
            mx0 = fmaxf(mx0, fmaxf(s[nf][0], s[nf][1]));
            mx1 = fmaxf(mx1, fmaxf(s[nf][2], s[nf][3]));
        }
        mx0 = fmaxf(mx0, __shfl_xor_sync(0xffffffffu, mx0, 1));
        mx0 = fmaxf(mx0, __shfl_xor_sync(0xffffffffu, mx0, 2));
        mx1 = fmaxf(mx1, __shfl_xor_sync(0xffffffffu, mx1, 1));
        mx1 = fmaxf(mx1, __shfl_xor_sync(0xffffffffu, mx1, 2));
        float mn0 = fmaxf(m0, mx0), mn1 = fmaxf(m1, mx1);
        float al0 = __expf(m0 - mn0), al1 = __expf(m1 - mn1);
        float sum0 = 0.f, sum1 = 0.f;
#pragma unroll
        for (int nf = 0; nf < 4; nf++) {
            s[nf][0] = __expf(s[nf][0] - mn0);
            s[nf][1] = __expf(s[nf][1] - mn0);
            s[nf][2] = __expf(s[nf][2] - mn1);
            s[nf][3] = __expf(s[nf][3] - mn1);
            sum0 += s[nf][0] + s[nf][1];
            sum1 += s[nf][2] + s[nf][3];
        }
        sum0 += __shfl_xor_sync(0xffffffffu, sum0, 1);
        sum0 += __shfl_xor_sync(0xffffffffu, sum0, 2);
        sum1 += __shfl_xor_sync(0xffffffffu, sum1, 1);
        sum1 += __shfl_xor_sync(0xffffffffu, sum1, 2);
        l0 = l0 * al0 + sum0; l1 = l1 * al1 + sum1;
        m0 = mn0; m1 = mn1;
#pragma unroll
        for (int nf = 0; nf < 8; nf++) {
            acc_o[nf][0] *= al0; acc_o[nf][1] *= al0;
            acc_o[nf][2] *= al1; acc_o[nf][3] *= al1;
        }

#pragma unroll
        for (int nf = 0; nf < 4; nf++) {
            float2 p01; p01.x = s[nf][0]; p01.y = s[nf][1];
            float2 p23; p23.x = s[nf][2]; p23.y = s[nf][3];
            *(float2*)&Ps[r0][nf * 8 + 2 * fc]     = p01;
            *(float2*)&Ps[r0 + 8][nf * 8 + 2 * fc] = p23;
        }
        __syncwarp();

#pragma unroll
        for (int ks = 0; ks < 4; ks++) {
            const int kb = ks * 8;
            uint32_t a[4];
            a[0] = __float_as_uint(Ps[r0][kb + fc]);
            a[1] = __float_as_uint(Ps[r0 + 8][kb + fc]);
            a[2] = __float_as_uint(Ps[r0][kb + fc + 4]);
            a[3] = __float_as_uint(Ps[r0 + 8][kb + fc + 4]);
#pragma unroll
            for (int nf = 0; nf < 8; nf++) {
                uint32_t bb[2];
                bb[0] = __float_as_uint(Vs[kb + fc][nf * 8 + fr]);
                bb[1] = __float_as_uint(Vs[kb + fc + 4][nf * 8 + fr]);
                mma_tf32(acc_o[nf], a, bb);
            }
        }
        __syncthreads();
    }

    float inv0 = 1.0f / l0, inv1 = 1.0f / l1;
    const size_t obase = (size_t)(b * SEQ) * DIM + h * DH;
#pragma unroll
    for (int nf = 0; nf < 8; nf++) {
        int col = nf * 8 + 2 * fc;
        float2 o0; o0.x = acc_o[nf][0] * inv0; o0.y = acc_o[nf][1] * inv0;
        float2 o1; o1.x = acc_o[nf][2] * inv1; o1.y = acc_o[nf][3] * inv1;
        *(float2*)&out[obase + (size_t)(q0 + r0) * DIM + col]     = o0;
        *(float2*)&out[obase + (size_t)(q0 + r0 + 8) * DIM + col] = o1;
    }
}

// ---------------- launch ----------------------------------------------------
extern "C" void kernel_launch(void* const* d_in, const int* in_sizes, int n_in,
                              void* d_out, int out_size)
{
    const float* x      = (const float*)d_in[0];
    const float* w_qkv  = (const float*)d_in[1];
    const float* b_qkv  = (const float*)d_in[2];
    const float* w_proj = (const float*)d_in[3];
    const float* b_proj = (const float*)d_in[4];
    const float* w_fc1  = (const float*)d_in[5];
    const float* b_fc1  = (const float*)d_in[6];
    const float* w_fc2  = (const float*)d_in[7];
    const float* b_fc2  = (const float*)d_in[8];
    const float* g1     = (const float*)d_in[9];
    const float* beta1  = (const float*)d_in[10];
    const float* g2     = (const float*)d_in[11];
    const float* beta2  = (const float*)d_in[12];
    float* out = (float*)d_out;

    float *p_ln, *p_qkv, *p_attn, *p_x1, *p_h;
    cudaGetSymbolAddress((void**)&p_ln,   g_ln);
    cudaGetSymbolAddress((void**)&p_qkv,  g_qkv);
    cudaGetSymbolAddress((void**)&p_attn, g_attn);
    cudaGetSymbolAddress((void**)&p_x1,   g_x1);
    cudaGetSymbolAddress((void**)&p_h,    g_h);

    cudaFuncSetAttribute(gemm_tc<0>, cudaFuncAttributeMaxDynamicSharedMemorySize, GEMM_SMEM);
    cudaFuncSetAttribute(gemm_tc<1>, cudaFuncAttributeMaxDynamicSharedMemorySize, GEMM_SMEM);
    cudaFuncSetAttribute(gemm_tc<2>, cudaFuncAttributeMaxDynamicSharedMemorySize, GEMM_SMEM);

    // 1) LN1
    ln_kernel<<<NTOK / 8, 256>>>(x, g1, beta1, p_ln);
    // 2) QKV GEMM: [8192,384] @ [384,1152] + bias
    gemm_tc<0><<<dim3(3 * DIM / 128, NTOK / 128), 256, GEMM_SMEM>>>(
        p_ln, w_qkv, b_qkv, nullptr, p_qkv, NTOK, DIM, 3 * DIM);
    // 3) tf32 tensor-core flash attention
    attn_tc<<<dim3(SEQ / 64, BATCH * HEADS), 128>>>(p_qkv, p_attn);
    // 4) proj GEMM + bias + residual(x)
    gemm_tc<2><<<dim3(DIM / 128, NTOK / 128), 256, GEMM_SMEM>>>(
        p_attn, w_proj, b_proj, x, p_x1, NTOK, DIM, DIM);
    // 5) LN2
    ln_kernel<<<NTOK / 8, 256>>>(p_x1, g2, beta2, p_ln);
    // 6) FC1 GEMM + bias + exact GELU
    gemm_tc<1><<<dim3(HID / 128, NTOK / 128), 256, GEMM_SMEM>>>(
        p_ln, w_fc1, b_fc1, nullptr, p_h, NTOK, DIM, HID);
    // 7) FC2 GEMM + bias + residual(x1) -> d_out
    gemm_tc<2><<<dim3(DIM / 128, NTOK / 128), 256, GEMM_SMEM>>>(
        p_h, w_fc2, b_fc2, p_x1, out, NTOK, HID, DIM);
}